// round 10
// baseline (speedup 1.0000x reference)
#include <cuda_runtime.h>
#include <cuda_bf16.h>

// Tensor-core LSTM, R10: bias via MMA C-operand (no accumulator-init movs),
// sigmoid 0.5-scale folded into i/f/o weights, 2 warps per SMSP (64 CTAs x
// 256 threads). One warp owns 8 batch elements; mma.sync.m16n8k16 bf16;
// packed bf16x2 cell math; L2(i) || L1(i+1) cross-layer pipeline.

#define FULLMASK 0xffffffffu
#define LOG2E 1.4426950408889634f
#define H2C 0x3F003F00u   /* bf16x2 {0.5, 0.5} */

typedef unsigned int u32;

static __device__ __forceinline__ u32 packb2(float lo, float hi) {
    u32 d;
    asm("cvt.rn.bf16x2.f32 %0, %1, %2;" : "=r"(d) : "f"(hi), "f"(lo));
    return d;
}
static __device__ __forceinline__ u32 tanhb2(u32 x) {
    u32 y; asm("tanh.approx.bf16x2 %0, %1;" : "=r"(y) : "r"(x)); return y;
}
static __device__ __forceinline__ u32 mulb2(u32 a, u32 b) {
    u32 d; asm("mul.rn.bf16x2 %0, %1, %2;" : "=r"(d) : "r"(a), "r"(b)); return d;
}
static __device__ __forceinline__ u32 fmab2(u32 a, u32 b, u32 c) {
    u32 d; asm("fma.rn.bf16x2 %0, %1, %2, %3;" : "=r"(d) : "r"(a), "r"(b), "r"(c));
    return d;
}
static __device__ __forceinline__ float blo(u32 v) {
    return __uint_as_float(v << 16);
}
static __device__ __forceinline__ float bhi(u32 v) {
    return __uint_as_float(v & 0xFFFF0000u);
}
static __device__ __forceinline__ float ex2f(float x) {
    float y; asm("ex2.approx.f32 %0, %1;" : "=f"(y) : "f"(x)); return y;
}
static __device__ __forceinline__ float rcpf(float x) {
    float y; asm("rcp.approx.f32 %0, %1;" : "=f"(y) : "f"(x)); return y;
}

// D = A @ B + C  (C separate input: bias splat {c0,c1,c0,c1} with no movs)
static __device__ __forceinline__ void mma_c(
    float* d, u32 a0, u32 a2, u32 b0, u32 b1, float c0, float c1)
{
    asm("mma.sync.aligned.m16n8k16.row.col.f32.bf16.bf16.f32 "
        "{%0,%1,%2,%3},{%4,%5,%6,%7},{%8,%9},{%10,%11,%10,%11};"
        : "=f"(d[0]), "=f"(d[1]), "=f"(d[2]), "=f"(d[3])
        : "r"(a0), "r"(a0), "r"(a2), "r"(a2), "r"(b0), "r"(b1),
          "f"(c0), "f"(c1));
}
// D += A @ B (accumulate in place)
static __device__ __forceinline__ void mma_acc(
    float* d, u32 a0, u32 a2, u32 b0, u32 b1)
{
    asm("mma.sync.aligned.m16n8k16.row.col.f32.bf16.bf16.f32 "
        "{%0,%1,%2,%3},{%4,%5,%6,%7},{%8,%9},{%0,%1,%2,%3};"
        : "+f"(d[0]), "+f"(d[1]), "+f"(d[2]), "+f"(d[3])
        : "r"(a0), "r"(a0), "r"(a2), "r"(a2), "r"(b0), "r"(b1));
}

// packed 2-cell LSTM update; i/f/o gate inputs arrive PRE-SCALED by 0.5
// (folded into weights), so sigmoid = fma(tanh(gate), 0.5, 0.5) directly.
#define PCELL(IP, FP, GP, OP, CC, HH) do {                                \
    u32 si_ = fmab2(tanhb2(IP), H2C, H2C);                                \
    u32 sf_ = fmab2(tanhb2(FP), H2C, H2C);                                \
    u32 tg_ = tanhb2(GP);                                                 \
    u32 so_ = fmab2(tanhb2(OP), H2C, H2C);                                \
    CC = fmab2(sf_, CC, mulb2(si_, tg_));                                 \
    HH = mulb2(so_, tanhb2(CC));                                          \
} while (0)

__global__ void __launch_bounds__(256)
lstm_mma_kernel(const float* __restrict__ x,
                const float* __restrict__ Wih1, const float* __restrict__ Whh1,
                const float* __restrict__ bih1, const float* __restrict__ bhh1,
                const float* __restrict__ Wih2, const float* __restrict__ Whh2,
                const float* __restrict__ bih2, const float* __restrict__ bhh2,
                const float* __restrict__ Wd1, const float* __restrict__ bd1,
                const float* __restrict__ Wd2, const float* __restrict__ bd2,
                const float* __restrict__ Wd3, const float* __restrict__ bd3,
                float* __restrict__ out)
{
    constexpr int T = 512, IN = 11;
    const int tid  = threadIdx.x;
    const int lane = tid & 31;
    const int wid  = tid >> 5;           // 0..7
    const int q    = lane & 3;
    const int g    = lane >> 2;
    const int k0   = q * 2;
    const int eb   = blockIdx.x * 64;    // CTA batch base (64 elems)

    // x staging: [phase][step-in-chunk][elem][8 bf16x2]; chunk c holds t=4c+1..4c+4
    __shared__ __align__(16) u32 xs[2][4][64][8];
    __shared__ float sbuf[64][16];

    // gate scale: tiles 0-3 (i,f) and 6,7 (o) get 0.5; tiles 4,5 (g) get 1.0
    // ---- weight B-fragments; layer-1 bias folded at K index 11 ----
    u32 w1i[8][2], w1h[8][2], w2i[8][2], w2h[8][2];
    float bs2f[8][2];
#pragma unroll
    for (int t = 0; t < 8; ++t) {
        const float gs = (t == 4 || t == 5) ? 1.0f : 0.5f;
        const int n = t * 8 + g;
        {
            float a0 = (k0     < IN) ? Wih1[n * IN + k0]     : 0.f;
            float a1 = (k0 + 1 < IN) ? Wih1[n * IN + k0 + 1] : 0.f;
            float a8 = (k0 + 8 < IN) ? Wih1[n * IN + k0 + 8] : 0.f;
            float a9 = (k0 + 9 < IN) ? Wih1[n * IN + k0 + 9]
                     : (k0 + 9 == 11 ? (bih1[n] + bhh1[n]) : 0.f);
            w1i[t][0] = packb2(gs * a0, gs * a1);
            w1i[t][1] = packb2(gs * a8, gs * a9);
        }
        w1h[t][0] = packb2(gs * Whh1[n * 16 + k0],     gs * Whh1[n * 16 + k0 + 1]);
        w1h[t][1] = packb2(gs * Whh1[n * 16 + k0 + 8], gs * Whh1[n * 16 + k0 + 9]);
        w2i[t][0] = packb2(gs * Wih2[n * 16 + k0],     gs * Wih2[n * 16 + k0 + 1]);
        w2i[t][1] = packb2(gs * Wih2[n * 16 + k0 + 8], gs * Wih2[n * 16 + k0 + 9]);
        w2h[t][0] = packb2(gs * Whh2[n * 16 + k0],     gs * Whh2[n * 16 + k0 + 1]);
        w2h[t][1] = packb2(gs * Whh2[n * 16 + k0 + 8], gs * Whh2[n * 16 + k0 + 9]);
        const int col = t * 8 + k0;
        bs2f[t][0] = gs * (bih2[col]     + bhh2[col]);
        bs2f[t][1] = gs * (bih2[col + 1] + bhh2[col + 1]);
    }

    // ---- x staging: thread -> (elem = tid>>2, step-in-chunk = tid&3) ----
    const int se = tid >> 2;             // 0..63 (CTA-local elem)
    const int ss = tid & 3;
    const float* xp = x + ((size_t)(eb + se) * T + (ss + 1)) * IN;

    // stage chunk 0 (t = 1..4); x[11] slot = 1.0 carries the layer-1 bias
    {
        float xr[11];
#pragma unroll
        for (int i = 0; i < 11; ++i) xr[i] = __ldg(xp + i);
        u32* d = &xs[0][ss][se][0];
        d[0] = packb2(xr[0], xr[1]); d[1] = packb2(xr[2], xr[3]);
        d[2] = packb2(xr[4], xr[5]); d[3] = packb2(xr[6], xr[7]);
        d[4] = packb2(xr[8], xr[9]); d[5] = packb2(xr[10], 1.0f);
        d[6] = 0u; d[7] = 0u;
    }
    __syncwarp();

    const int elw = wid * 8 + g;         // this lane's CTA-local elem (0..63)

    // recurrent state (packed bf16x2)
    u32 h1c0 = 0, h1c2 = 0;              // h1(i)
    u32 h2p0 = 0, h2p2 = 0;              // h2(i-1)
    u32 c1p0 = 0, c1p1 = 0, c2p0 = 0, c2p1 = 0;
    float ss0 = 0.f, ss1 = 0.f, ss2 = 0.f, ss3 = 0.f;

    // ---- prologue: h1(0) = cell(Wih1·x(0) + b1) ----
    {
        const float* x0 = x + (size_t)(eb + elw) * T * IN;
        float a0 = (k0     < IN) ? __ldg(x0 + k0)     : 0.f;
        float a1 = (k0 + 1 < IN) ? __ldg(x0 + k0 + 1) : 0.f;
        float a8 = (k0 + 8 < IN) ? __ldg(x0 + k0 + 8) : 0.f;
        float a9 = (k0 + 9 < IN) ? __ldg(x0 + k0 + 9) : (k0 + 9 == 11 ? 1.f : 0.f);
        u32 xa0 = packb2(a0, a1);
        u32 xa2 = packb2(a8, a9);
        float A[8][4];
#pragma unroll
        for (int t = 0; t < 8; ++t)
            mma_c(A[t], xa0, xa2, w1i[t][0], w1i[t][1], 0.f, 0.f);
        u32 iP0 = packb2(A[0][0], A[0][1]), iP1 = packb2(A[1][0], A[1][1]);
        u32 fP0 = packb2(A[2][0], A[2][1]), fP1 = packb2(A[3][0], A[3][1]);
        u32 gP0 = packb2(A[4][0], A[4][1]), gP1 = packb2(A[5][0], A[5][1]);
        u32 oP0 = packb2(A[6][0], A[6][1]), oP1 = packb2(A[7][0], A[7][1]);
        PCELL(iP0, fP0, gP0, oP0, c1p0, h1c0);
        PCELL(iP1, fP1, gP1, oP1, c1p1, h1c2);
    }

    // ---- main loop: iter i = 4c+s computes L2(i) || L1(i+1); skip i=511 ----
    for (int c = 0; c < 128; ++c) {
        float xr[11] = {0,0,0,0,0,0,0,0,0,0,0};
        if (c < 127) {
            const float* xq = xp + (size_t)(c + 1) * 4 * IN;   // t = 4c+ss+5
            if (4 * c + ss + 5 < T) {
#pragma unroll
                for (int i = 0; i < 11; ++i) xr[i] = __ldg(xq + i);
            }
        }

#pragma unroll
        for (int s = 0; s < 4; ++s) {
            if (c == 127 && s == 3) break;   // iter 511 handled in epilogue
            const u32* xrow = &xs[c & 1][s][elw][0];
            const u32 xa0 = xrow[q];
            const u32 xa2 = xrow[q + 4];

            float A[8][4], Bq[8][4];
            // all 32 MMAs independent; bias enters via C operand (no init movs)
#pragma unroll
            for (int t = 0; t < 8; ++t) {
                mma_c  (A[t],  h1c0, h1c2, w2i[t][0], w2i[t][1],
                        bs2f[t][0], bs2f[t][1]);
                mma_acc(A[t],  h2p0, h2p2, w2h[t][0], w2h[t][1]);
                mma_c  (Bq[t], h1c0, h1c2, w1h[t][0], w1h[t][1], 0.f, 0.f);
                mma_acc(Bq[t], xa0,  xa2,  w1i[t][0], w1i[t][1]);
            }

            // L2 cell -> h2(i)
            {
                u32 iP0 = packb2(A[0][0], A[0][1]), iP1 = packb2(A[1][0], A[1][1]);
                u32 fP0 = packb2(A[2][0], A[2][1]), fP1 = packb2(A[3][0], A[3][1]);
                u32 gP0 = packb2(A[4][0], A[4][1]), gP1 = packb2(A[5][0], A[5][1]);
                u32 oP0 = packb2(A[6][0], A[6][1]), oP1 = packb2(A[7][0], A[7][1]);
                PCELL(iP0, fP0, gP0, oP0, c2p0, h2p0);
                PCELL(iP1, fP1, gP1, oP1, c2p1, h2p2);
                ss0 += ex2f(blo(h2p0) * LOG2E);
                ss1 += ex2f(bhi(h2p0) * LOG2E);
                ss2 += ex2f(blo(h2p2) * LOG2E);
                ss3 += ex2f(bhi(h2p2) * LOG2E);
            }
            // L1 cell -> h1(i+1)
            {
                u32 iP0 = packb2(Bq[0][0], Bq[0][1]), iP1 = packb2(Bq[1][0], Bq[1][1]);
                u32 fP0 = packb2(Bq[2][0], Bq[2][1]), fP1 = packb2(Bq[3][0], Bq[3][1]);
                u32 gP0 = packb2(Bq[4][0], Bq[4][1]), gP1 = packb2(Bq[5][0], Bq[5][1]);
                u32 oP0 = packb2(Bq[6][0], Bq[6][1]), oP1 = packb2(Bq[7][0], Bq[7][1]);
                PCELL(iP0, fP0, gP0, oP0, c1p0, h1c0);
                PCELL(iP1, fP1, gP1, oP1, c1p1, h1c2);
            }
        }

        if (c < 127) {
            u32* d = &xs[(c + 1) & 1][ss][se][0];
            d[0] = packb2(xr[0], xr[1]); d[1] = packb2(xr[2], xr[3]);
            d[2] = packb2(xr[4], xr[5]); d[3] = packb2(xr[6], xr[7]);
            d[4] = packb2(xr[8], xr[9]); d[5] = packb2(xr[10], 1.0f);
            d[6] = 0u; d[7] = 0u;
        }
        __syncwarp();
    }

    // ---- epilogue: L2(511) ----
    {
        float A[8][4];
#pragma unroll
        for (int t = 0; t < 8; ++t) {
            mma_c  (A[t], h1c0, h1c2, w2i[t][0], w2i[t][1],
                    bs2f[t][0], bs2f[t][1]);
            mma_acc(A[t], h2p0, h2p2, w2h[t][0], w2h[t][1]);
        }
        u32 iP0 = packb2(A[0][0], A[0][1]), iP1 = packb2(A[1][0], A[1][1]);
        u32 fP0 = packb2(A[2][0], A[2][1]), fP1 = packb2(A[3][0], A[3][1]);
        u32 gP0 = packb2(A[4][0], A[4][1]), gP1 = packb2(A[5][0], A[5][1]);
        u32 oP0 = packb2(A[6][0], A[6][1]), oP1 = packb2(A[7][0], A[7][1]);
        PCELL(iP0, fP0, gP0, oP0, c2p0, h2p0);
        PCELL(iP1, fP1, gP1, oP1, c2p1, h2p2);
        ss0 += ex2f(blo(h2p0) * LOG2E);
        ss1 += ex2f(bhi(h2p0) * LOG2E);
        ss2 += ex2f(blo(h2p2) * LOG2E);
        ss3 += ex2f(bhi(h2p2) * LOG2E);
    }

    // ---- s = exp(h2_last)/ssum per (elem, hcol) ----
    sbuf[elw][k0]     = ex2f(blo(h2p0) * LOG2E) * rcpf(ss0);
    sbuf[elw][k0 + 1] = ex2f(bhi(h2p0) * LOG2E) * rcpf(ss1);
    sbuf[elw][k0 + 8] = ex2f(blo(h2p2) * LOG2E) * rcpf(ss2);
    sbuf[elw][k0 + 9] = ex2f(bhi(h2p2) * LOG2E) * rcpf(ss3);
    __syncwarp();

    // ---- dense head: lanes 0-7 of each warp handle its 8 elems ----
    if (lane < 8) {
        const float* sr = &sbuf[wid * 8 + lane][0];
        float d1[8];
#pragma unroll
        for (int r = 0; r < 8; ++r) {
            float acc = bd1[r];
#pragma unroll
            for (int k = 0; k < 16; ++k)
                acc = fmaf(__ldg(Wd1 + r * 16 + k), sr[k], acc);
            d1[r] = acc;
        }
        float d2[8];
#pragma unroll
        for (int r = 0; r < 8; ++r) {
            float acc = bd2[r];
#pragma unroll
            for (int k = 0; k < 8; ++k)
                acc = fmaf(__ldg(Wd2 + r * 8 + k), d1[k], acc);
            d2[r] = acc;
        }
        float d3[3];
#pragma unroll
        for (int r = 0; r < 3; ++r) {
            float acc = bd3[r];
#pragma unroll
            for (int k = 0; k < 8; ++k)
                acc = fmaf(__ldg(Wd3 + r * 8 + k), d2[k], acc);
            d3[r] = acc;
        }
        float m  = fmaxf(d3[0], fmaxf(d3[1], d3[2]));
        float e0 = ex2f((d3[0] - m) * LOG2E);
        float e1 = ex2f((d3[1] - m) * LOG2E);
        float e2 = ex2f((d3[2] - m) * LOG2E);
        float inv = rcpf(e0 + e1 + e2);
        const int bg = eb + wid * 8 + lane;
        out[bg * 3 + 0] = e0 * inv;
        out[bg * 3 + 1] = e1 * inv;
        out[bg * 3 + 2] = e2 * inv;
    }
}

extern "C" void kernel_launch(void* const* d_in, const int* in_sizes, int n_in,
                              void* d_out, int out_size) {
    (void)in_sizes; (void)n_in; (void)out_size;
    const float* x    = (const float*)d_in[0];
    const float* Wih1 = (const float*)d_in[1];
    const float* Whh1 = (const float*)d_in[2];
    const float* bih1 = (const float*)d_in[3];
    const float* bhh1 = (const float*)d_in[4];
    const float* Wih2 = (const float*)d_in[5];
    const float* Whh2 = (const float*)d_in[6];
    const float* bih2 = (const float*)d_in[7];
    const float* bhh2 = (const float*)d_in[8];
    const float* Wd1  = (const float*)d_in[9];
    const float* bd1  = (const float*)d_in[10];
    const float* Wd2  = (const float*)d_in[11];
    const float* bd2  = (const float*)d_in[12];
    const float* Wd3  = (const float*)d_in[13];
    const float* bd3  = (const float*)d_in[14];
    float* out = (float*)d_out;

    // 4096 elems / (8 warps x 8 elems) = 64 CTAs; 2 warps per SMSP
    lstm_mma_kernel<<<64, 256>>>(x, Wih1, Whh1, bih1, bhh1,
                                 Wih2, Whh2, bih2, bhh2,
                                 Wd1, bd1, Wd2, bd2, Wd3, bd3, out);
}

// round 11
// speedup vs baseline: 1.5848x; 1.5848x over previous
#include <cuda_runtime.h>
#include <cuda_bf16.h>

// Tensor-core LSTM, R11 = R8 geometry (128 CTAs x 128 thr, full SM coverage)
// + R10 instruction trims: bias via MMA C-operand (no accumulator-init movs),
// sigmoid 0.5-scale folded into i/f/o weights, L2(i) || L1(i+1) pipeline.
// One warp owns 8 batch elements; mma.sync.m16n8k16 bf16; packed bf16x2 cell.

#define FULLMASK 0xffffffffu
#define LOG2E 1.4426950408889634f
#define H2C 0x3F003F00u   /* bf16x2 {0.5, 0.5} */

typedef unsigned int u32;

static __device__ __forceinline__ u32 packb2(float lo, float hi) {
    u32 d;
    asm("cvt.rn.bf16x2.f32 %0, %1, %2;" : "=r"(d) : "f"(hi), "f"(lo));
    return d;
}
static __device__ __forceinline__ u32 tanhb2(u32 x) {
    u32 y; asm("tanh.approx.bf16x2 %0, %1;" : "=r"(y) : "r"(x)); return y;
}
static __device__ __forceinline__ u32 mulb2(u32 a, u32 b) {
    u32 d; asm("mul.rn.bf16x2 %0, %1, %2;" : "=r"(d) : "r"(a), "r"(b)); return d;
}
static __device__ __forceinline__ u32 fmab2(u32 a, u32 b, u32 c) {
    u32 d; asm("fma.rn.bf16x2 %0, %1, %2, %3;" : "=r"(d) : "r"(a), "r"(b), "r"(c));
    return d;
}
static __device__ __forceinline__ float blo(u32 v) {
    return __uint_as_float(v << 16);
}
static __device__ __forceinline__ float bhi(u32 v) {
    return __uint_as_float(v & 0xFFFF0000u);
}
static __device__ __forceinline__ float ex2f(float x) {
    float y; asm("ex2.approx.f32 %0, %1;" : "=f"(y) : "f"(x)); return y;
}
static __device__ __forceinline__ float rcpf(float x) {
    float y; asm("rcp.approx.f32 %0, %1;" : "=f"(y) : "f"(x)); return y;
}

// D = A @ B + C  (C separate: bias splat {c0,c1,c0,c1}, no init movs)
static __device__ __forceinline__ void mma_c(
    float* d, u32 a0, u32 a2, u32 b0, u32 b1, float c0, float c1)
{
    asm("mma.sync.aligned.m16n8k16.row.col.f32.bf16.bf16.f32 "
        "{%0,%1,%2,%3},{%4,%5,%6,%7},{%8,%9},{%10,%11,%10,%11};"
        : "=f"(d[0]), "=f"(d[1]), "=f"(d[2]), "=f"(d[3])
        : "r"(a0), "r"(a0), "r"(a2), "r"(a2), "r"(b0), "r"(b1),
          "f"(c0), "f"(c1));
}
// D += A @ B (accumulate in place)
static __device__ __forceinline__ void mma_acc(
    float* d, u32 a0, u32 a2, u32 b0, u32 b1)
{
    asm("mma.sync.aligned.m16n8k16.row.col.f32.bf16.bf16.f32 "
        "{%0,%1,%2,%3},{%4,%5,%6,%7},{%8,%9},{%0,%1,%2,%3};"
        : "+f"(d[0]), "+f"(d[1]), "+f"(d[2]), "+f"(d[3])
        : "r"(a0), "r"(a0), "r"(a2), "r"(a2), "r"(b0), "r"(b1));
}

// packed 2-cell LSTM update; i/f/o gate inputs arrive PRE-SCALED by 0.5
// (folded into weights/biases), so sigmoid = fma(tanh(gate), 0.5, 0.5).
#define PCELL(IP, FP, GP, OP, CC, HH) do {                                \
    u32 si_ = fmab2(tanhb2(IP), H2C, H2C);                                \
    u32 sf_ = fmab2(tanhb2(FP), H2C, H2C);                                \
    u32 tg_ = tanhb2(GP);                                                 \
    u32 so_ = fmab2(tanhb2(OP), H2C, H2C);                                \
    CC = fmab2(sf_, CC, mulb2(si_, tg_));                                 \
    HH = mulb2(so_, tanhb2(CC));                                          \
} while (0)

__global__ void __launch_bounds__(128)
lstm_mma_kernel(const float* __restrict__ x,
                const float* __restrict__ Wih1, const float* __restrict__ Whh1,
                const float* __restrict__ bih1, const float* __restrict__ bhh1,
                const float* __restrict__ Wih2, const float* __restrict__ Whh2,
                const float* __restrict__ bih2, const float* __restrict__ bhh2,
                const float* __restrict__ Wd1, const float* __restrict__ bd1,
                const float* __restrict__ Wd2, const float* __restrict__ bd2,
                const float* __restrict__ Wd3, const float* __restrict__ bd3,
                float* __restrict__ out)
{
    constexpr int T = 512, IN = 11;
    const int tid  = threadIdx.x;
    const int lane = tid & 31;
    const int wid  = tid >> 5;           // 0..3
    const int q    = lane & 3;
    const int g    = lane >> 2;
    const int k0   = q * 2;
    const int eb   = blockIdx.x * 32;    // CTA batch base (32 elems)

    // x staging: [phase][step-in-chunk][elem][8 bf16x2]; chunk c holds t=4c+1..4c+4
    __shared__ __align__(16) u32 xs[2][4][32][8];
    __shared__ float sbuf[32][16];

    // ---- weight B-fragments; layer-1 bias folded at K index 11;
    //      0.5 sigmoid scale folded into i (t=0,1), f (t=2,3), o (t=6,7) ----
    u32 w1i[8][2], w1h[8][2], w2i[8][2], w2h[8][2];
    float bs2f[8][2];
#pragma unroll
    for (int t = 0; t < 8; ++t) {
        const float gs = (t == 4 || t == 5) ? 1.0f : 0.5f;
        const int n = t * 8 + g;
        {
            float a0 = (k0     < IN) ? Wih1[n * IN + k0]     : 0.f;
            float a1 = (k0 + 1 < IN) ? Wih1[n * IN + k0 + 1] : 0.f;
            float a8 = (k0 + 8 < IN) ? Wih1[n * IN + k0 + 8] : 0.f;
            float a9 = (k0 + 9 < IN) ? Wih1[n * IN + k0 + 9]
                     : (k0 + 9 == 11 ? (bih1[n] + bhh1[n]) : 0.f);
            w1i[t][0] = packb2(gs * a0, gs * a1);
            w1i[t][1] = packb2(gs * a8, gs * a9);
        }
        w1h[t][0] = packb2(gs * Whh1[n * 16 + k0],     gs * Whh1[n * 16 + k0 + 1]);
        w1h[t][1] = packb2(gs * Whh1[n * 16 + k0 + 8], gs * Whh1[n * 16 + k0 + 9]);
        w2i[t][0] = packb2(gs * Wih2[n * 16 + k0],     gs * Wih2[n * 16 + k0 + 1]);
        w2i[t][1] = packb2(gs * Wih2[n * 16 + k0 + 8], gs * Wih2[n * 16 + k0 + 9]);
        w2h[t][0] = packb2(gs * Whh2[n * 16 + k0],     gs * Whh2[n * 16 + k0 + 1]);
        w2h[t][1] = packb2(gs * Whh2[n * 16 + k0 + 8], gs * Whh2[n * 16 + k0 + 9]);
        const int col = t * 8 + k0;
        bs2f[t][0] = gs * (bih2[col]     + bhh2[col]);
        bs2f[t][1] = gs * (bih2[col + 1] + bhh2[col + 1]);
    }

    // ---- x staging: thread -> (elem = tid>>2, step-in-chunk = tid&3) ----
    const int se = tid >> 2;             // 0..31 (CTA-local elem)
    const int ss = tid & 3;
    const float* xp = x + ((size_t)(eb + se) * T + (ss + 1)) * IN;

    // stage chunk 0 (t = 1..4); x[11] slot = 1.0 carries the layer-1 bias
    {
        float xr[11];
#pragma unroll
        for (int i = 0; i < 11; ++i) xr[i] = __ldg(xp + i);
        u32* d = &xs[0][ss][se][0];
        d[0] = packb2(xr[0], xr[1]); d[1] = packb2(xr[2], xr[3]);
        d[2] = packb2(xr[4], xr[5]); d[3] = packb2(xr[6], xr[7]);
        d[4] = packb2(xr[8], xr[9]); d[5] = packb2(xr[10], 1.0f);
        d[6] = 0u; d[7] = 0u;
    }
    __syncwarp();

    const int elw = wid * 8 + g;         // this lane's CTA-local elem (0..31)

    // recurrent state (packed bf16x2)
    u32 h1c0 = 0, h1c2 = 0;              // h1(i)
    u32 h2p0 = 0, h2p2 = 0;              // h2(i-1)
    u32 c1p0 = 0, c1p1 = 0, c2p0 = 0, c2p1 = 0;
    float ss0 = 0.f, ss1 = 0.f, ss2 = 0.f, ss3 = 0.f;

    // ---- prologue: h1(0) = cell(Wih1·x(0) + b1) ----
    {
        const float* x0 = x + (size_t)(eb + elw) * T * IN;
        float a0 = (k0     < IN) ? __ldg(x0 + k0)     : 0.f;
        float a1 = (k0 + 1 < IN) ? __ldg(x0 + k0 + 1) : 0.f;
        float a8 = (k0 + 8 < IN) ? __ldg(x0 + k0 + 8) : 0.f;
        float a9 = (k0 + 9 < IN) ? __ldg(x0 + k0 + 9) : (k0 + 9 == 11 ? 1.f : 0.f);
        u32 xa0 = packb2(a0, a1);
        u32 xa2 = packb2(a8, a9);
        float A[8][4];
#pragma unroll
        for (int t = 0; t < 8; ++t)
            mma_c(A[t], xa0, xa2, w1i[t][0], w1i[t][1], 0.f, 0.f);
        u32 iP0 = packb2(A[0][0], A[0][1]), iP1 = packb2(A[1][0], A[1][1]);
        u32 fP0 = packb2(A[2][0], A[2][1]), fP1 = packb2(A[3][0], A[3][1]);
        u32 gP0 = packb2(A[4][0], A[4][1]), gP1 = packb2(A[5][0], A[5][1]);
        u32 oP0 = packb2(A[6][0], A[6][1]), oP1 = packb2(A[7][0], A[7][1]);
        PCELL(iP0, fP0, gP0, oP0, c1p0, h1c0);
        PCELL(iP1, fP1, gP1, oP1, c1p1, h1c2);
    }

    // ---- main loop: iter i = 4c+s computes L2(i) || L1(i+1); skip i=511 ----
    for (int c = 0; c < 128; ++c) {
        float xr[11] = {0,0,0,0,0,0,0,0,0,0,0};
        if (c < 127) {
            const float* xq = xp + (size_t)(c + 1) * 4 * IN;   // t = 4c+ss+5
            if (4 * c + ss + 5 < T) {
#pragma unroll
                for (int i = 0; i < 11; ++i) xr[i] = __ldg(xq + i);
            }
        }

#pragma unroll
        for (int s = 0; s < 4; ++s) {
            if (c == 127 && s == 3) break;   // iter 511 handled in epilogue
            const u32* xrow = &xs[c & 1][s][elw][0];
            const u32 xa0 = xrow[q];
            const u32 xa2 = xrow[q + 4];

            float A[8][4], Bq[8][4];
            // all 32 MMAs independent; bias enters via C operand
#pragma unroll
            for (int t = 0; t < 8; ++t) {
                mma_c  (A[t],  h1c0, h1c2, w2i[t][0], w2i[t][1],
                        bs2f[t][0], bs2f[t][1]);
                mma_acc(A[t],  h2p0, h2p2, w2h[t][0], w2h[t][1]);
                mma_c  (Bq[t], h1c0, h1c2, w1h[t][0], w1h[t][1], 0.f, 0.f);
                mma_acc(Bq[t], xa0,  xa2,  w1i[t][0], w1i[t][1]);
            }

            // L2 cell -> h2(i)
            {
                u32 iP0 = packb2(A[0][0], A[0][1]), iP1 = packb2(A[1][0], A[1][1]);
                u32 fP0 = packb2(A[2][0], A[2][1]), fP1 = packb2(A[3][0], A[3][1]);
                u32 gP0 = packb2(A[4][0], A[4][1]), gP1 = packb2(A[5][0], A[5][1]);
                u32 oP0 = packb2(A[6][0], A[6][1]), oP1 = packb2(A[7][0], A[7][1]);
                PCELL(iP0, fP0, gP0, oP0, c2p0, h2p0);
                PCELL(iP1, fP1, gP1, oP1, c2p1, h2p2);
                ss0 += ex2f(blo(h2p0) * LOG2E);
                ss1 += ex2f(bhi(h2p0) * LOG2E);
                ss2 += ex2f(blo(h2p2) * LOG2E);
                ss3 += ex2f(bhi(h2p2) * LOG2E);
            }
            // L1 cell -> h1(i+1)
            {
                u32 iP0 = packb2(Bq[0][0], Bq[0][1]), iP1 = packb2(Bq[1][0], Bq[1][1]);
                u32 fP0 = packb2(Bq[2][0], Bq[2][1]), fP1 = packb2(Bq[3][0], Bq[3][1]);
                u32 gP0 = packb2(Bq[4][0], Bq[4][1]), gP1 = packb2(Bq[5][0], Bq[5][1]);
                u32 oP0 = packb2(Bq[6][0], Bq[6][1]), oP1 = packb2(Bq[7][0], Bq[7][1]);
                PCELL(iP0, fP0, gP0, oP0, c1p0, h1c0);
                PCELL(iP1, fP1, gP1, oP1, c1p1, h1c2);
            }
        }

        if (c < 127) {
            u32* d = &xs[(c + 1) & 1][ss][se][0];
            d[0] = packb2(xr[0], xr[1]); d[1] = packb2(xr[2], xr[3]);
            d[2] = packb2(xr[4], xr[5]); d[3] = packb2(xr[6], xr[7]);
            d[4] = packb2(xr[8], xr[9]); d[5] = packb2(xr[10], 1.0f);
            d[6] = 0u; d[7] = 0u;
        }
        __syncwarp();
    }

    // ---- epilogue: L2(511) ----
    {
        float A[8][4];
#pragma unroll
        for (int t = 0; t < 8; ++t) {
            mma_c  (A[t], h1c0, h1c2, w2i[t][0], w2i[t][1],
                    bs2f[t][0], bs2f[t][1]);
            mma_acc(A[t], h2p0, h2p2, w2h[t][0], w2h[t][1]);
        }
        u32 iP0 = packb2(A[0][0], A[0][1]), iP1 = packb2(A[1][0], A[1][1]);
        u32 fP0 = packb2(A[2][0], A[2][1]), fP1 = packb2(A[3][0], A[3][1]);
        u32 gP0 = packb2(A[4][0], A[4][1]), gP1 = packb2(A[5][0], A[5][1]);
        u32 oP0 = packb2(A[6][0], A[6][1]), oP1 = packb2(A[7][0], A[7][1]);
        PCELL(iP0, fP0, gP0, oP0, c2p0, h2p0);
        PCELL(iP1, fP1, gP1, oP1, c2p1, h2p2);
        ss0 += ex2f(blo(h2p0) * LOG2E);
        ss1 += ex2f(bhi(h2p0) * LOG2E);
        ss2 += ex2f(blo(h2p2) * LOG2E);
        ss3 += ex2f(bhi(h2p2) * LOG2E);
    }

    // ---- s = exp(h2_last)/ssum per (elem, hcol) ----
    sbuf[elw][k0]     = ex2f(blo(h2p0) * LOG2E) * rcpf(ss0);
    sbuf[elw][k0 + 1] = ex2f(bhi(h2p0) * LOG2E) * rcpf(ss1);
    sbuf[elw][k0 + 8] = ex2f(blo(h2p2) * LOG2E) * rcpf(ss2);
    sbuf[elw][k0 + 9] = ex2f(bhi(h2p2) * LOG2E) * rcpf(ss3);
    __syncwarp();

    // ---- dense head: lanes 0-7 of each warp handle its 8 elems ----
    if (lane < 8) {
        const float* sr = &sbuf[wid * 8 + lane][0];
        float d1[8];
#pragma unroll
        for (int r = 0; r < 8; ++r) {
            float acc = bd1[r];
#pragma unroll
            for (int k = 0; k < 16; ++k)
                acc = fmaf(__ldg(Wd1 + r * 16 + k), sr[k], acc);
            d1[r] = acc;
        }
        float d2[8];
#pragma unroll
        for (int r = 0; r < 8; ++r) {
            float acc = bd2[r];
#pragma unroll
            for (int k = 0; k < 8; ++k)
                acc = fmaf(__ldg(Wd2 + r * 8 + k), d1[k], acc);
            d2[r] = acc;
        }
        float d3[3];
#pragma unroll
        for (int r = 0; r < 3; ++r) {
            float acc = bd3[r];
#pragma unroll
            for (int k = 0; k < 8; ++k)
                acc = fmaf(__ldg(Wd3 + r * 8 + k), d2[k], acc);
            d3[r] = acc;
        }
        float m  = fmaxf(d3[0], fmaxf(d3[1], d3[2]));
        float e0 = ex2f((d3[0] - m) * LOG2E);
        float e1 = ex2f((d3[1] - m) * LOG2E);
        float e2 = ex2f((d3[2] - m) * LOG2E);
        float inv = rcpf(e0 + e1 + e2);
        const int bg = eb + wid * 8 + lane;
        out[bg * 3 + 0] = e0 * inv;
        out[bg * 3 + 1] = e1 * inv;
        out[bg * 3 + 2] = e2 * inv;
    }
}

extern "C" void kernel_launch(void* const* d_in, const int* in_sizes, int n_in,
                              void* d_out, int out_size) {
    (void)in_sizes; (void)n_in; (void)out_size;
    const float* x    = (const float*)d_in[0];
    const float* Wih1 = (const float*)d_in[1];
    const float* Whh1 = (const float*)d_in[2];
    const float* bih1 = (const float*)d_in[3];
    const float* bhh1 = (const float*)d_in[4];
    const float* Wih2 = (const float*)d_in[5];
    const float* Whh2 = (const float*)d_in[6];
    const float* bih2 = (const float*)d_in[7];
    const float* bhh2 = (const float*)d_in[8];
    const float* Wd1  = (const float*)d_in[9];
    const float* bd1  = (const float*)d_in[10];
    const float* Wd2  = (const float*)d_in[11];
    const float* bd2  = (const float*)d_in[12];
    const float* Wd3  = (const float*)d_in[13];
    const float* bd3  = (const float*)d_in[14];
    float* out = (float*)d_out;

    // 4096 elems / (4 warps x 8 elems) = 128 CTAs — full SM coverage, 1 wave
    lstm_mma_kernel<<<128, 128>>>(x, Wih1, Whh1, bih1, bhh1,
                                  Wih2, Whh2, bih2, bhh2,
                                  Wd1, bd1, Wd2, bd2, Wd3, bd3, out);
}